// round 5
// baseline (speedup 1.0000x reference)
#include <cuda_runtime.h>
#include <math_constants.h>

#define NC 64
#define BLOCK 256

__global__ __launch_bounds__(BLOCK)
void energy_well_kernel(const float2* __restrict__ pos,
                        const float2* __restrict__ half_sz,
                        const float4* __restrict__ well_boxes,
                        const unsigned int* __restrict__ avail,  // int32 flags, 64/row
                        const float* __restrict__ expo,
                        float* __restrict__ out,
                        int n)
{
    __shared__ unsigned int smask[BLOCK * 2];   // 64-bit avail mask per row (2KB)
    __shared__ float sxl[8], sxh[8], syl[8], syh[8];

    int t = threadIdx.x;
    if (t < 8) {
        // 8x8 grid: wells 0..7 span the x-extents; wells 0,8,..,56 span the y-extents.
        float4 bx = well_boxes[t];
        sxl[t] = bx.x; sxh[t] = bx.z;
        float4 by = well_boxes[t * 8];
        syl[t] = by.y; syh[t] = by.w;
    }

    int rowBase = blockIdx.x * BLOCK;
    int validInts = (n - rowBase) * NC;
    if (validInts > BLOCK * NC) validInts = BLOCK * NC;
    const unsigned int* g = avail + (size_t)rowBase * NC;

    // ---- Stage: 64 coalesced 32-bit loads/thread, ballot-compress to 1 bit/flag ----
#pragma unroll
    for (int b = 0; b < 8; b++) {
        unsigned int v[8];
#pragma unroll
        for (int u = 0; u < 8; u++) {
            int idx = (b * 8 + u) * BLOCK + t;
            v[u] = (idx < validInts) ? g[idx] : 0u;
        }
#pragma unroll
        for (int u = 0; u < 8; u++) {
            int idx = (b * 8 + u) * BLOCK + t;
            unsigned int bal = __ballot_sync(0xFFFFFFFFu, v[u] != 0u);
            if ((t & 31) == 0) smask[idx >> 5] = bal;   // idx>>5 is warp-uniform
        }
    }
    __syncthreads();

    int i = rowBase + t;
    if (i >= n) return;

    float2 p = pos[i];
    float2 h = half_sz[i];
    float xlo = p.x - h.x, xhi = p.x + h.x;
    float ylo = p.y - h.y, yhi = p.y + h.y;

    // Separable distances: 8 column dx, 8 row dy
    float dxv[8], dyv[8];
#pragma unroll
    for (int k = 0; k < 8; k++) {
        dxv[k] = fmaxf(fmaxf(sxl[k] - xlo, xhi - sxh[k]), 0.0f);
        dyv[k] = fmaxf(fmaxf(syl[k] - ylo, yhi - syh[k]), 0.0f);
    }

    unsigned int mlo = smask[2 * t];
    unsigned int mhi = smask[2 * t + 1];

    // Two independent argmin chains (first-index wins ties within chains; merge
    // prefers chain A, whose indices are all lower).
    float dA = CUDART_INF_F; int cA = 0;
    float dB = CUDART_INF_F; int cB = 32;
#pragma unroll
    for (int j = 0; j < 4; j++) {
#pragma unroll
        for (int k = 0; k < 8; k++) {
            int c = j * 8 + k;
            bool av = (mlo >> c) & 1u;
            float d = dxv[k] + dyv[j];
            if (av && d < dA) { dA = d; cA = c; }
        }
    }
#pragma unroll
    for (int j = 4; j < 8; j++) {
#pragma unroll
        for (int k = 0; k < 8; k++) {
            int c = j * 8 + k;
            bool av = (mhi >> (c - 32)) & 1u;
            float d = dxv[k] + dyv[j];
            if (av && d < dB) { dB = d; cB = c; }
        }
    }
    int bc = (dB < dA) ? cB : cA;

    // Recompute dx/dy of the selected well (identical ops -> bit-exact)
    int cx = bc & 7, cy = bc >> 3;
    float fdx = fmaxf(fmaxf(sxl[cx] - xlo, xhi - sxh[cx]), 0.0f);
    float fdy = fmaxf(fmaxf(syl[cy] - ylo, yhi - syh[cy]), 0.0f);

    float e = expo[i];
    out[i] = (e == 2.0f) ? (fdx * fdx + fdy * fdy)
                         : (powf(fdx, e) + powf(fdy, e));
}

extern "C" void kernel_launch(void* const* d_in, const int* in_sizes, int n_in,
                              void* d_out, int out_size)
{
    // 0: inst_pos (N,2) f32 | 1: half_inst_sizes (N,2) f32 | 2: inst_areas (unused)
    // 3: well_boxes (64,4) f32 | 4: inst_cr_avail_map (N,64) bool->int32 | 5: exponents (N,) f32
    const float2* pos     = (const float2*)d_in[0];
    const float2* half_sz = (const float2*)d_in[1];
    const float4* wb      = (const float4*)d_in[3];
    const unsigned int* avail = (const unsigned int*)d_in[4];
    const float* expo     = (const float*)d_in[5];
    float* out = (float*)d_out;

    int n = out_size;
    int blocks = (n + BLOCK - 1) / BLOCK;
    energy_well_kernel<<<blocks, BLOCK>>>(pos, half_sz, wb, avail, expo, out, n);
}

// round 9
// speedup vs baseline: 1.1112x; 1.1112x over previous
#include <cuda_runtime.h>
#include <math_constants.h>

#define NC 64
#define BLOCK 256
#define WARPS (BLOCK / 32)

__global__ __launch_bounds__(BLOCK)
void energy_well_kernel(const float2* __restrict__ pos,
                        const float2* __restrict__ half_sz,
                        const float4* __restrict__ well_boxes,
                        const uint4* __restrict__ avail4,  // int32 flags, 16 uint4/row
                        const float* __restrict__ expo,
                        float* __restrict__ out,
                        int n)
{
    __shared__ uint4 sball[WARPS][16];               // ballot pieces, 2KB
    __shared__ float sxl[8], sxh[8], syl[8], syh[8]; // 8x8 grid extents

    int t = threadIdx.x;
    int lane = t & 31;
    int warp = t >> 5;

    if (t < 8) {
        float4 bx = well_boxes[t];       // wells 0..7: x extents
        sxl[t] = bx.x; sxh[t] = bx.z;
        float4 by = well_boxes[t * 8];   // wells 0,8,..,56: y extents
        syl[t] = by.y; syh[t] = by.w;
    }

    // ---- Warp-local staging: coalesced LDG.128 + ballot compression ----
    int slabRow = blockIdx.x * BLOCK + warp * 32;    // first row of this warp's slab
    int vr = n - slabRow;                            // valid rows in slab
    if (vr > 32) vr = 32;
    if (vr < 0) vr = 0;
    int vchunks = vr * 16;                           // valid uint4 chunks
    const uint4* g4 = avail4 + (size_t)slabRow * 16 + lane;

    // Front-batch all 16 LDG.128 (predicated, no divergent branch) for max MLP.
    uint4 av[16];
#pragma unroll
    for (int k = 0; k < 16; k++) {
        uint4 a = make_uint4(0u, 0u, 0u, 0u);
        if (k * 32 + lane < vchunks) a = g4[k * 32];
        av[k] = a;
    }
#pragma unroll
    for (int k = 0; k < 16; k++) {
        // bit l of ballot j = flag 4*(l&15)+j of row 2k + (l>=16)
        unsigned int b0 = __ballot_sync(0xFFFFFFFFu, av[k].x != 0u);
        unsigned int b1 = __ballot_sync(0xFFFFFFFFu, av[k].y != 0u);
        unsigned int b2 = __ballot_sync(0xFFFFFFFFu, av[k].z != 0u);
        unsigned int b3 = __ballot_sync(0xFFFFFFFFu, av[k].w != 0u);
        if (lane == 0) sball[warp][k] = make_uint4(b0, b1, b2, b3);
    }
    __syncthreads();

    int i = blockIdx.x * BLOCK + t;
    if (i >= n) return;

    // My row's 4 mask pieces: bit q of m[j] = avail[i][4q+j], q=0..15
    uint4 pc = sball[warp][lane >> 1];
    int sh = (lane & 1) * 16;
    unsigned int m0 = (pc.x >> sh) & 0xFFFFu;
    unsigned int m1 = (pc.y >> sh) & 0xFFFFu;
    unsigned int m2 = (pc.z >> sh) & 0xFFFFu;
    unsigned int m3 = (pc.w >> sh) & 0xFFFFu;

    float2 p = pos[i];
    float2 h = half_sz[i];
    float xlo = p.x - h.x, xhi = p.x + h.x;
    float ylo = p.y - h.y, yhi = p.y + h.y;

    // Separable distances: 8 column dx, 8 row dy
    float dxv[8], dyv[8];
#pragma unroll
    for (int k = 0; k < 8; k++) {
        dxv[k] = fmaxf(fmaxf(sxl[k] - xlo, xhi - sxh[k]), 0.0f);
        dyv[k] = fmaxf(fmaxf(syl[k] - ylo, yhi - syh[k]), 0.0f);
    }

    // Two independent argmin chains over c = 4q + j (ascending -> first-index ties).
    // Chain A: q 0..7 (c < 32). Chain B: q 8..15 (c >= 32). Merge prefers A on ties.
    float dA = CUDART_INF_F, axA = 0.0f, ayA = 0.0f;
    float dB = CUDART_INF_F, axB = 0.0f, ayB = 0.0f;
#pragma unroll
    for (int q = 0; q < 8; q++) {
#pragma unroll
        for (int j = 0; j < 4; j++) {
            const int c = 4 * q + j;
            unsigned int mj = (j == 0) ? m0 : (j == 1) ? m1 : (j == 2) ? m2 : m3;
            bool av_ = (mj >> q) & 1u;
            float fx = dxv[c & 7], fy = dyv[c >> 3];
            float d = fx + fy;
            if (av_ && d < dA) { dA = d; axA = fx; ayA = fy; }
        }
    }
#pragma unroll
    for (int q = 8; q < 16; q++) {
#pragma unroll
        for (int j = 0; j < 4; j++) {
            const int c = 4 * q + j;
            unsigned int mj = (j == 0) ? m0 : (j == 1) ? m1 : (j == 2) ? m2 : m3;
            bool av_ = (mj >> q) & 1u;
            float fx = dxv[c & 7], fy = dyv[c >> 3];
            float d = fx + fy;
            if (av_ && d < dB) { dB = d; axB = fx; ayB = fy; }
        }
    }
    float fdx = (dB < dA) ? axB : axA;
    float fdy = (dB < dA) ? ayB : ayA;

    float e = expo[i];
    out[i] = (e == 2.0f) ? (fdx * fdx + fdy * fdy)
                         : (powf(fdx, e) + powf(fdy, e));
}

extern "C" void kernel_launch(void* const* d_in, const int* in_sizes, int n_in,
                              void* d_out, int out_size)
{
    // 0: inst_pos (N,2) f32 | 1: half_inst_sizes (N,2) f32 | 2: inst_areas (unused)
    // 3: well_boxes (64,4) f32 | 4: inst_cr_avail_map (N,64) bool->int32 | 5: exponents (N,) f32
    const float2* pos     = (const float2*)d_in[0];
    const float2* half_sz = (const float2*)d_in[1];
    const float4* wb      = (const float4*)d_in[3];
    const uint4* avail4   = (const uint4*)d_in[4];
    const float* expo     = (const float*)d_in[5];
    float* out = (float*)d_out;

    int n = out_size;
    int blocks = (n + BLOCK - 1) / BLOCK;
    energy_well_kernel<<<blocks, BLOCK>>>(pos, half_sz, wb, avail4, expo, out, n);
}

// round 10
// speedup vs baseline: 1.2221x; 1.0998x over previous
#include <cuda_runtime.h>
#include <math_constants.h>

#define NC 64
#define BLOCK 256
#define WARPS (BLOCK / 32)

__global__ __launch_bounds__(BLOCK)
void energy_well_kernel(const float2* __restrict__ pos,
                        const float2* __restrict__ half_sz,
                        const float4* __restrict__ well_boxes,
                        const uint4* __restrict__ avail4,  // int32 flags, 16 uint4/row
                        const float* __restrict__ expo,
                        float* __restrict__ out,
                        int n)
{
    __shared__ uint4 sball[WARPS][16];               // ballot pieces, 2KB
    __shared__ float sxl[8], sxh[8], syl[8], syh[8]; // 8x8 grid extents

    int t = threadIdx.x;
    int lane = t & 31;
    int warp = t >> 5;

    if (t < 8) {
        float4 bx = well_boxes[t];       // wells 0..7: x extents
        sxl[t] = bx.x; sxh[t] = bx.z;
        float4 by = well_boxes[t * 8];   // wells 0,8,..,56: y extents
        syl[t] = by.y; syh[t] = by.w;
    }

    int i = blockIdx.x * BLOCK + t;
    // Hoist per-instance scalar loads so they overlap the avail stream.
    float2 p = make_float2(0.f, 0.f), h = make_float2(0.f, 0.f);
    float e = 2.0f;
    if (i < n) { p = pos[i]; h = half_sz[i]; e = expo[i]; }

    // ---- Warp-local staging: coalesced LDG.128 + ballot compression ----
    int slabRow = blockIdx.x * BLOCK + warp * 32;
    int vr = n - slabRow;
    if (vr > 32) vr = 32;
    if (vr < 0) vr = 0;
    int vchunks = vr * 16;
    const uint4* g4 = avail4 + (size_t)slabRow * 16 + lane;

    uint4 av[16];
#pragma unroll
    for (int k = 0; k < 16; k++) {
        uint4 a = make_uint4(0u, 0u, 0u, 0u);
        if (k * 32 + lane < vchunks) a = g4[k * 32];
        av[k] = a;
    }
#pragma unroll
    for (int k = 0; k < 16; k++) {
        unsigned int b0 = __ballot_sync(0xFFFFFFFFu, av[k].x != 0u);
        unsigned int b1 = __ballot_sync(0xFFFFFFFFu, av[k].y != 0u);
        unsigned int b2 = __ballot_sync(0xFFFFFFFFu, av[k].z != 0u);
        unsigned int b3 = __ballot_sync(0xFFFFFFFFu, av[k].w != 0u);
        if (lane == 0) sball[warp][k] = make_uint4(b0, b1, b2, b3);
    }
    __syncthreads();

    if (i >= n) return;

    // My row's 4 mask pieces: bit q of m[j] = avail[i][4q+j], q=0..15
    uint4 pc = sball[warp][lane >> 1];
    int sh = (lane & 1) * 16;
    unsigned int m0 = (pc.x >> sh) & 0xFFFFu;
    unsigned int m1 = (pc.y >> sh) & 0xFFFFu;
    unsigned int m2 = (pc.z >> sh) & 0xFFFFu;
    unsigned int m3 = (pc.w >> sh) & 0xFFFFu;

    float xlo = p.x - h.x, xhi = p.x + h.x;
    float ylo = p.y - h.y, yhi = p.y + h.y;

    // Separable distances: 8 column dx, 8 row dy
    float dxv[8], dyv[8];
#pragma unroll
    for (int k = 0; k < 8; k++) {
        dxv[k] = fmaxf(fmaxf(sxl[k] - xlo, xhi - sxh[k]), 0.0f);
        dyv[k] = fmaxf(fmaxf(syl[k] - ylo, yhi - syh[k]), 0.0f);
    }

    // 8 independent argmin chains; chain r covers c = 8r..8r+7 (ascending ->
    // first-index tie-break inside a chain). Short chains break the serial
    // FSETP->FSEL dependency that throttled issue.
    float bd[8], bfx[8], bfy[8];
#pragma unroll
    for (int r = 0; r < 8; r++) { bd[r] = CUDART_INF_F; bfx[r] = 0.0f; bfy[r] = 0.0f; }

#pragma unroll
    for (int q = 0; q < 16; q++) {
        const int r = q >> 1;
#pragma unroll
        for (int j = 0; j < 4; j++) {
            const int c = 4 * q + j;
            unsigned int mj = (j == 0) ? m0 : (j == 1) ? m1 : (j == 2) ? m2 : m3;
            bool ok = (mj >> q) & 1u;
            float fx = dxv[c & 7], fy = dyv[c >> 3];
            float d = fx + fy;
            if (ok && d < bd[r]) { bd[r] = d; bfx[r] = fx; bfy[r] = fy; }
        }
    }

    // Log-tree merge; strictly-less from the higher chain, so the lower chain
    // (smaller well indices) wins ties -> exact argmin-first semantics.
#pragma unroll
    for (int s = 1; s < 8; s <<= 1) {
#pragma unroll
        for (int r = 0; r < 8; r += 2 * s) {
            bool takeB = bd[r + s] < bd[r];
            bd[r]  = takeB ? bd[r + s]  : bd[r];
            bfx[r] = takeB ? bfx[r + s] : bfx[r];
            bfy[r] = takeB ? bfy[r + s] : bfy[r];
        }
    }
    float fdx = bfx[0], fdy = bfy[0];

    out[i] = (e == 2.0f) ? (fdx * fdx + fdy * fdy)
                         : (powf(fdx, e) + powf(fdy, e));
}

extern "C" void kernel_launch(void* const* d_in, const int* in_sizes, int n_in,
                              void* d_out, int out_size)
{
    // 0: inst_pos (N,2) f32 | 1: half_inst_sizes (N,2) f32 | 2: inst_areas (unused)
    // 3: well_boxes (64,4) f32 | 4: inst_cr_avail_map (N,64) bool->int32 | 5: exponents (N,) f32
    const float2* pos     = (const float2*)d_in[0];
    const float2* half_sz = (const float2*)d_in[1];
    const float4* wb      = (const float4*)d_in[3];
    const uint4* avail4   = (const uint4*)d_in[4];
    const float* expo     = (const float*)d_in[5];
    float* out = (float*)d_out;

    int n = out_size;
    int blocks = (n + BLOCK - 1) / BLOCK;
    energy_well_kernel<<<blocks, BLOCK>>>(pos, half_sz, wb, avail4, expo, out, n);
}

// round 12
// speedup vs baseline: 1.2321x; 1.0082x over previous
#include <cuda_runtime.h>
#include <math_constants.h>

#define NC 64
#define BLOCK 256
#define WARPS (BLOCK / 32)

__global__ __launch_bounds__(BLOCK)
void energy_well_kernel(const float2* __restrict__ pos,
                        const float2* __restrict__ half_sz,
                        const float4* __restrict__ well_boxes,
                        const uint4* __restrict__ avail4,  // int32 flags, 16 uint4/row
                        const float* __restrict__ expo,
                        float* __restrict__ out,
                        int n)
{
    __shared__ uint4 sball[WARPS][16];               // ballot pieces, 2KB
    __shared__ float sxl[8], sxh[8], syl[8], syh[8]; // 8x8 grid extents

    int t = threadIdx.x;
    int lane = t & 31;
    int warp = t >> 5;

    if (t < 8) {
        float4 bx = well_boxes[t];       // wells 0..7: x extents
        sxl[t] = bx.x; sxh[t] = bx.z;
        float4 by = well_boxes[t * 8];   // wells 0,8,..,56: y extents
        syl[t] = by.y; syh[t] = by.w;
    }

    int i = blockIdx.x * BLOCK + t;

    // ---- Warp-local staging: 4 rounds of (4x LDG.128 -> ballots -> STS) ----
    // Bounded liveness (4 uint4 = 16 regs) keeps total regs low -> high occ.
    int slabRow = blockIdx.x * BLOCK + warp * 32;
    int vr = n - slabRow;
    if (vr > 32) vr = 32;
    if (vr < 0) vr = 0;
    int vchunks = vr * 16;
    const uint4* g4 = avail4 + (size_t)slabRow * 16 + lane;

#pragma unroll
    for (int grp = 0; grp < 4; grp++) {
        uint4 a[4];
#pragma unroll
        for (int k2 = 0; k2 < 4; k2++) {
            int k = grp * 4 + k2;
            uint4 v = make_uint4(0u, 0u, 0u, 0u);
            if (k * 32 + lane < vchunks) v = g4[k * 32];
            a[k2] = v;
        }
#pragma unroll
        for (int k2 = 0; k2 < 4; k2++) {
            int k = grp * 4 + k2;
            // bit l of ballot j = flag 4*(l&15)+j of row 2k + (l>=16)
            unsigned int b0 = __ballot_sync(0xFFFFFFFFu, a[k2].x != 0u);
            unsigned int b1 = __ballot_sync(0xFFFFFFFFu, a[k2].y != 0u);
            unsigned int b2 = __ballot_sync(0xFFFFFFFFu, a[k2].z != 0u);
            unsigned int b3 = __ballot_sync(0xFFFFFFFFu, a[k2].w != 0u);
            if (lane == 0) sball[warp][k] = make_uint4(b0, b1, b2, b3);
        }
    }
    __syncthreads();

    if (i >= n) return;

    // Per-instance scalars (L2/L1-resident after first touch; tiny streams).
    float2 p = pos[i];
    float2 h = half_sz[i];
    float e = expo[i];

    // My row's 4 mask pieces: bit q of m[j] = avail[i][4q+j], q=0..15
    uint4 pc = sball[warp][lane >> 1];
    int sh = (lane & 1) * 16;
    unsigned int m0 = (pc.x >> sh) & 0xFFFFu;
    unsigned int m1 = (pc.y >> sh) & 0xFFFFu;
    unsigned int m2 = (pc.z >> sh) & 0xFFFFu;
    unsigned int m3 = (pc.w >> sh) & 0xFFFFu;

    float xlo = p.x - h.x, xhi = p.x + h.x;
    float ylo = p.y - h.y, yhi = p.y + h.y;

    // Separable distances: 8 column dx, 8 row dy
    float dxv[8], dyv[8];
#pragma unroll
    for (int k = 0; k < 8; k++) {
        dxv[k] = fmaxf(fmaxf(sxl[k] - xlo, xhi - sxh[k]), 0.0f);
        dyv[k] = fmaxf(fmaxf(syl[k] - ylo, yhi - syh[k]), 0.0f);
    }

    // 8 independent argmin chains; chain r covers c = 8r..8r+7 (ascending ->
    // first-index tie-break inside a chain).
    float bd[8], bfx[8], bfy[8];
#pragma unroll
    for (int r = 0; r < 8; r++) { bd[r] = CUDART_INF_F; bfx[r] = 0.0f; bfy[r] = 0.0f; }

#pragma unroll
    for (int q = 0; q < 16; q++) {
        const int r = q >> 1;
#pragma unroll
        for (int j = 0; j < 4; j++) {
            const int c = 4 * q + j;
            unsigned int mj = (j == 0) ? m0 : (j == 1) ? m1 : (j == 2) ? m2 : m3;
            bool ok = (mj >> q) & 1u;
            float fx = dxv[c & 7], fy = dyv[c >> 3];
            float d = fx + fy;
            if (ok && d < bd[r]) { bd[r] = d; bfx[r] = fx; bfy[r] = fy; }
        }
    }

    // Log-tree merge; strictly-less from the higher chain keeps lower-index
    // priority -> exact argmin-first semantics.
#pragma unroll
    for (int s = 1; s < 8; s <<= 1) {
#pragma unroll
        for (int r = 0; r < 8; r += 2 * s) {
            bool takeB = bd[r + s] < bd[r];
            bd[r]  = takeB ? bd[r + s]  : bd[r];
            bfx[r] = takeB ? bfx[r + s] : bfx[r];
            bfy[r] = takeB ? bfy[r + s] : bfy[r];
        }
    }
    float fdx = bfx[0], fdy = bfy[0];

    out[i] = (e == 2.0f) ? (fdx * fdx + fdy * fdy)
                         : (powf(fdx, e) + powf(fdy, e));
}

extern "C" void kernel_launch(void* const* d_in, const int* in_sizes, int n_in,
                              void* d_out, int out_size)
{
    // 0: inst_pos (N,2) f32 | 1: half_inst_sizes (N,2) f32 | 2: inst_areas (unused)
    // 3: well_boxes (64,4) f32 | 4: inst_cr_avail_map (N,64) bool->int32 | 5: exponents (N,) f32
    const float2* pos     = (const float2*)d_in[0];
    const float2* half_sz = (const float2*)d_in[1];
    const float4* wb      = (const float4*)d_in[3];
    const uint4* avail4   = (const uint4*)d_in[4];
    const float* expo     = (const float*)d_in[5];
    float* out = (float*)d_out;

    int n = out_size;
    int blocks = (n + BLOCK - 1) / BLOCK;
    energy_well_kernel<<<blocks, BLOCK>>>(pos, half_sz, wb, avail4, expo, out, n);
}